// round 7
// baseline (speedup 1.0000x reference)
#include <cuda_runtime.h>
#include <math.h>

#define BATCH  256
#define SEQ    128
#define HID    1024
#define KHEADS 4
#define GDIM   16384   // 4 * HID * KHEADS

// ---------------- scratch state (no allocations allowed) ----------------
__device__ __align__(16) float g_gates[BATCH * GDIM];          // 16 MB gates scratch
__device__ __align__(16) float g_c[BATCH * KHEADS * HID];      // 4 MB cell state
__device__ __align__(16) float g_h[2][BATCH * HID];            // double-buffered hidden

__device__ __forceinline__ float sigmoidf_(float x) {
    return 1.0f / (1.0f + expf(-x));
}

// ---------------- init h0 = 0, c0 = 0 ----------------
__global__ void zero_kernel() {
    int idx = blockIdx.x * blockDim.x + threadIdx.x;
    if (idx < BATCH * HID)          g_h[0][idx] = 0.0f;
    if (idx < BATCH * KHEADS * HID) g_c[idx]    = 0.0f;
}

// ---------------- recurrent gates GEMM ----------------
// gates[b, g] = sum_k h[b,k] * Wh[k,g]   + Wi[X[b,t], g] + bi[g] + bh[g]
// Tiling: 128x128x8, 256 threads, 8x8 per-thread register tile, double-buffered smem.
#define BM  128
#define BN  128
#define BKK 8
#define TM  8
#define TN  8

__global__ __launch_bounds__(256, 2)
void gemm_gates_kernel(const float* __restrict__ Wh,
                       const float* __restrict__ Wi,
                       const float* __restrict__ bi,
                       const float* __restrict__ bh,
                       const int*   __restrict__ X,
                       int t, int hbuf)
{
    __shared__ float As[2][BKK][BM];
    __shared__ float Bs[2][BKK][BN];

    const float* __restrict__ A = g_h[hbuf];   // [BATCH, HID]
    const int m0  = blockIdx.y * BM;
    const int n0  = blockIdx.x * BN;
    const int tid = threadIdx.x;

    // global-load mapping
    const int a_m = tid >> 1;            // 0..127
    const int a_k = (tid & 1) << 2;      // 0 or 4
    const int b_k = tid >> 5;            // 0..7 (warp id)
    const int b_n = (tid & 31) << 2;     // 0..124

    // compute mapping
    const int tx = tid & 15;
    const int ty = tid >> 4;

    float acc[TM][TN];
#pragma unroll
    for (int i = 0; i < TM; ++i)
#pragma unroll
        for (int j = 0; j < TN; ++j) acc[i][j] = 0.0f;

    // prologue: k-tile 0
    {
        float4 av = *(const float4*)(A  + (m0 + a_m) * HID + a_k);
        float4 bv = *(const float4*)(Wh + b_k * GDIM + n0 + b_n);
        As[0][a_k + 0][a_m] = av.x; As[0][a_k + 1][a_m] = av.y;
        As[0][a_k + 2][a_m] = av.z; As[0][a_k + 3][a_m] = av.w;
        *(float4*)(&Bs[0][b_k][b_n]) = bv;
    }
    __syncthreads();

    const int KT = HID / BKK;   // 128
#pragma unroll 1
    for (int kt = 0; kt < KT; ++kt) {
        const int cur = kt & 1;
        float4 av, bv;
        if (kt + 1 < KT) {
            const int kk = (kt + 1) * BKK;
            av = *(const float4*)(A  + (m0 + a_m) * HID + kk + a_k);
            bv = *(const float4*)(Wh + (kk + b_k) * GDIM + n0 + b_n);
        }
#pragma unroll
        for (int k = 0; k < BKK; ++k) {
            float ar[TM], br[TN];
#pragma unroll
            for (int i = 0; i < TM; ++i) ar[i] = As[cur][k][ty * TM + i];
#pragma unroll
            for (int j = 0; j < TN; ++j) br[j] = Bs[cur][k][tx * TN + j];
#pragma unroll
            for (int i = 0; i < TM; ++i)
#pragma unroll
                for (int j = 0; j < TN; ++j)
                    acc[i][j] = fmaf(ar[i], br[j], acc[i][j]);
        }
        if (kt + 1 < KT) {
            const int nxt = cur ^ 1;
            As[nxt][a_k + 0][a_m] = av.x; As[nxt][a_k + 1][a_m] = av.y;
            As[nxt][a_k + 2][a_m] = av.z; As[nxt][a_k + 3][a_m] = av.w;
            *(float4*)(&Bs[nxt][b_k][b_n]) = bv;
            __syncthreads();
        }
    }

    // epilogue: + Wi[X[b,t], :] + bi + bh, write gates scratch
#pragma unroll
    for (int i = 0; i < TM; ++i) {
        const int gm = m0 + ty * TM + i;
        const int xb = X[gm * SEQ + t];
        const float* wrow = Wi + xb * GDIM;
        const int gn = n0 + tx * TN;
        float* orow = g_gates + gm * GDIM + gn;
#pragma unroll
        for (int j = 0; j < TN; j += 4) {
            float4 wv = *(const float4*)(wrow + gn + j);
            float4 b1 = *(const float4*)(bi + gn + j);
            float4 b2 = *(const float4*)(bh + gn + j);
            float4 o;
            o.x = acc[i][j + 0] + wv.x + b1.x + b2.x;
            o.y = acc[i][j + 1] + wv.y + b1.y + b2.y;
            o.z = acc[i][j + 2] + wv.z + b1.z + b2.z;
            o.w = acc[i][j + 3] + wv.w + b1.w + b2.w;
            *(float4*)(orow + j) = o;
        }
    }
}

// ---------------- pointwise LSTM update (activations + argmax head select) ----------------
// gates layout per row: index = k*4096 + gate*1024 + j  (gate: 0=i,1=f,2=g,3=o)
__global__ void lstm_update_kernel(int hnext) {
    const int idx = blockIdx.x * blockDim.x + threadIdx.x;  // 0 .. BATCH*HID-1
    const int b = idx >> 10;
    const int j = idx & (HID - 1);

    const float* gb = g_gates + b * GDIM + j;
    float* cb = g_c + (b * KHEADS) * HID + j;

    float omax = -3.402823466e38f;
    float csel = 0.0f;
#pragma unroll
    for (int k = 0; k < KHEADS; ++k) {
        const float gi = gb[k * 4096 + 0];
        const float gf = gb[k * 4096 + 1024];
        const float gg = gb[k * 4096 + 2048];
        const float go = gb[k * 4096 + 3072];
        const float iv = sigmoidf_(gi);
        const float fv = sigmoidf_(gf);
        const float gv = tanhf(gg);
        const float c  = fv * cb[k * HID] + iv * gv;
        cb[k * HID] = c;
        if (go > omax) { omax = go; csel = c; }  // strict > keeps first max (jnp.argmax)
    }
    g_h[hnext][idx] = sigmoidf_(omax) * tanhf(csel);
}

// ---------------- final logits GEMM: out = h @ Wl + bl ----------------
__global__ __launch_bounds__(256, 2)
void gemm_logits_kernel(const float* __restrict__ Wl,
                        const float* __restrict__ bl,
                        float* __restrict__ out,
                        int hbuf)
{
    __shared__ float As[2][BKK][BM];
    __shared__ float Bs[2][BKK][BN];

    const float* __restrict__ A = g_h[hbuf];
    const int m0  = blockIdx.y * BM;
    const int n0  = blockIdx.x * BN;
    const int tid = threadIdx.x;

    const int a_m = tid >> 1;
    const int a_k = (tid & 1) << 2;
    const int b_k = tid >> 5;
    const int b_n = (tid & 31) << 2;
    const int tx = tid & 15;
    const int ty = tid >> 4;

    float acc[TM][TN];
#pragma unroll
    for (int i = 0; i < TM; ++i)
#pragma unroll
        for (int j = 0; j < TN; ++j) acc[i][j] = 0.0f;

    {
        float4 av = *(const float4*)(A  + (m0 + a_m) * HID + a_k);
        float4 bv = *(const float4*)(Wl + b_k * HID + n0 + b_n);
        As[0][a_k + 0][a_m] = av.x; As[0][a_k + 1][a_m] = av.y;
        As[0][a_k + 2][a_m] = av.z; As[0][a_k + 3][a_m] = av.w;
        *(float4*)(&Bs[0][b_k][b_n]) = bv;
    }
    __syncthreads();

    const int KT = HID / BKK;
#pragma unroll 1
    for (int kt = 0; kt < KT; ++kt) {
        const int cur = kt & 1;
        float4 av, bv;
        if (kt + 1 < KT) {
            const int kk = (kt + 1) * BKK;
            av = *(const float4*)(A  + (m0 + a_m) * HID + kk + a_k);
            bv = *(const float4*)(Wl + (kk + b_k) * HID + n0 + b_n);
        }
#pragma unroll
        for (int k = 0; k < BKK; ++k) {
            float ar[TM], br[TN];
#pragma unroll
            for (int i = 0; i < TM; ++i) ar[i] = As[cur][k][ty * TM + i];
#pragma unroll
            for (int j = 0; j < TN; ++j) br[j] = Bs[cur][k][tx * TN + j];
#pragma unroll
            for (int i = 0; i < TM; ++i)
#pragma unroll
                for (int j = 0; j < TN; ++j)
                    acc[i][j] = fmaf(ar[i], br[j], acc[i][j]);
        }
        if (kt + 1 < KT) {
            const int nxt = cur ^ 1;
            As[nxt][a_k + 0][a_m] = av.x; As[nxt][a_k + 1][a_m] = av.y;
            As[nxt][a_k + 2][a_m] = av.z; As[nxt][a_k + 3][a_m] = av.w;
            *(float4*)(&Bs[nxt][b_k][b_n]) = bv;
            __syncthreads();
        }
    }

#pragma unroll
    for (int i = 0; i < TM; ++i) {
        const int gm = m0 + ty * TM + i;
        const int gn = n0 + tx * TN;
        float* orow = out + gm * HID + gn;
#pragma unroll
        for (int j = 0; j < TN; j += 4) {
            float4 b1 = *(const float4*)(bl + gn + j);
            float4 o;
            o.x = acc[i][j + 0] + b1.x;
            o.y = acc[i][j + 1] + b1.y;
            o.z = acc[i][j + 2] + b1.z;
            o.w = acc[i][j + 3] + b1.w;
            *(float4*)(orow + j) = o;
        }
    }
}

// ---------------- in-place log_softmax over rows of [BATCH, 1024] ----------------
__global__ void logsoftmax_kernel(float* __restrict__ out) {
    __shared__ float red[256];
    const int b = blockIdx.x;
    const int tid = threadIdx.x;
    float* row = out + b * HID;

    const float v0 = row[tid];
    const float v1 = row[tid + 256];
    const float v2 = row[tid + 512];
    const float v3 = row[tid + 768];

    float m = fmaxf(fmaxf(v0, v1), fmaxf(v2, v3));
    red[tid] = m;
    __syncthreads();
    for (int s = 128; s > 0; s >>= 1) {
        if (tid < s) red[tid] = fmaxf(red[tid], red[tid + s]);
        __syncthreads();
    }
    m = red[0];
    __syncthreads();

    float e = expf(v0 - m) + expf(v1 - m) + expf(v2 - m) + expf(v3 - m);
    red[tid] = e;
    __syncthreads();
    for (int s = 128; s > 0; s >>= 1) {
        if (tid < s) red[tid] += red[tid + s];
        __syncthreads();
    }
    const float lse = m + logf(red[0]);

    row[tid]       = v0 - lse;
    row[tid + 256] = v1 - lse;
    row[tid + 512] = v2 - lse;
    row[tid + 768] = v3 - lse;
}

// ---------------- launcher (graph-capturable: kernel launches only) ----------------
extern "C" void kernel_launch(void* const* d_in, const int* in_sizes, int n_in,
                              void* d_out, int out_size) {
    const int*   X  = (const int*)  d_in[0];
    const float* Wi = (const float*)d_in[1];
    const float* bi = (const float*)d_in[2];
    const float* Wh = (const float*)d_in[3];
    const float* bh = (const float*)d_in[4];
    const float* Wl = (const float*)d_in[5];
    const float* bl = (const float*)d_in[6];
    float* out = (float*)d_out;

    (void)in_sizes; (void)n_in; (void)out_size;

    // h0 = 0, c0 = 0
    zero_kernel<<<(BATCH * KHEADS * HID + 255) / 256, 256>>>();

    const dim3 gg(GDIM / BN, BATCH / BM);   // (128, 2)
    for (int t = 0; t < SEQ; ++t) {
        gemm_gates_kernel<<<gg, 256>>>(Wh, Wi, bi, bh, X, t, t & 1);
        lstm_update_kernel<<<(BATCH * HID) / 256, 256>>>((t + 1) & 1);
    }

    // final h lives in buffer 0 after 128 steps
    gemm_logits_kernel<<<dim3(HID / BN, BATCH / BM), 256>>>(Wl, bl, out, 0);
    logsoftmax_kernel<<<BATCH, 256>>>(out);
}

// round 9
// speedup vs baseline: 2.1690x; 2.1690x over previous
#include <cuda_runtime.h>
#include <cuda_bf16.h>
#include <math.h>
#include <stdint.h>

#define BATCH  256
#define SEQ    128
#define HID    1024
#define KHEADS 4
#define GDIM   16384   // 4 * HID * KHEADS

// ---------------- scratch state (no allocations allowed) ----------------
__device__ __align__(16) float g_gates[BATCH * GDIM];            // 16 MB gates scratch
__device__ __align__(16) float g_c[BATCH * KHEADS * HID];        // 4 MB cell state
__device__ __align__(16) float g_h[BATCH * HID];                 // hidden (fp32, for logits)
__device__ __align__(16) __nv_bfloat16 g_hhi[BATCH * HID];       // hidden hi (bf16)
__device__ __align__(16) __nv_bfloat16 g_hlo[BATCH * HID];       // hidden lo (bf16)
__device__ __align__(16) __nv_bfloat16 g_WhT_hi[(size_t)GDIM * HID];   // Wh^T hi  [n][k]
__device__ __align__(16) __nv_bfloat16 g_WhT_lo[(size_t)GDIM * HID];   // Wh^T lo  [n][k]
__device__ __align__(16) float g_bsum[GDIM];                     // bi + bh

__device__ __forceinline__ float sigmoidf_(float x) {
    return 1.0f / (1.0f + expf(-x));
}

// ====================== PTX helpers (baseline ISA only — no tcgen05) ======================
__device__ __forceinline__ uint32_t smem_u32(const void* p) {
    uint32_t a;
    asm("{ .reg .u64 t; cvta.to.shared.u64 t, %1; cvt.u32.u64 %0, t; }" : "=r"(a) : "l"(p));
    return a;
}
__device__ __forceinline__ void cp_async16(uint32_t dst, const void* src) {
    asm volatile("cp.async.cg.shared.global [%0], [%1], 16;" :: "r"(dst), "l"(src));
}
#define CP_COMMIT() asm volatile("cp.async.commit_group;" ::: "memory")
#define CP_WAIT(n)  asm volatile("cp.async.wait_group %0;" :: "n"(n) : "memory")

__device__ __forceinline__ void ldsm_x4(uint32_t r[4], uint32_t addr) {
    asm volatile("ldmatrix.sync.aligned.m8n8.x4.shared.b16 {%0,%1,%2,%3}, [%4];"
                 : "=r"(r[0]), "=r"(r[1]), "=r"(r[2]), "=r"(r[3]) : "r"(addr));
}
__device__ __forceinline__ void mma16816(float d[4], const uint32_t a[4], const uint32_t b[2]) {
    asm volatile(
        "mma.sync.aligned.m16n8k16.row.col.f32.bf16.bf16.f32 "
        "{%0,%1,%2,%3}, {%4,%5,%6,%7}, {%8,%9}, {%0,%1,%2,%3};"
        : "+f"(d[0]), "+f"(d[1]), "+f"(d[2]), "+f"(d[3])
        : "r"(a[0]), "r"(a[1]), "r"(a[2]), "r"(a[3]), "r"(b[0]), "r"(b[1]));
}

// ====================== prepass kernels ======================
// Wh [HID][GDIM] fp32 -> WhT hi/lo [GDIM][HID] bf16 (K-major = "col" B operand)
__global__ void prep_wht_kernel(const float* __restrict__ Wh) {
    __shared__ float tile[32][33];
    const int n0 = blockIdx.x * 32;
    const int k0 = blockIdx.y * 32;
    const int tx = threadIdx.x;   // 0..31
    const int ty = threadIdx.y;   // 0..7
#pragma unroll
    for (int i = 0; i < 4; ++i)
        tile[ty + i * 8][tx] = Wh[(size_t)(k0 + ty + i * 8) * GDIM + n0 + tx];
    __syncthreads();
#pragma unroll
    for (int i = 0; i < 4; ++i) {
        const float v = tile[tx][ty + i * 8];
        const __nv_bfloat16 hi = __float2bfloat16(v);
        const __nv_bfloat16 lo = __float2bfloat16(v - __bfloat162float(hi));
        const size_t o = (size_t)(n0 + ty + i * 8) * HID + k0 + tx;
        g_WhT_hi[o] = hi;
        g_WhT_lo[o] = lo;
    }
}

__global__ void prep_bsum_kernel(const float* __restrict__ bi, const float* __restrict__ bh) {
    const int i = blockIdx.x * blockDim.x + threadIdx.x;
    if (i < GDIM) g_bsum[i] = bi[i] + bh[i];
}

__global__ void zero_kernel() {
    const int idx = blockIdx.x * blockDim.x + threadIdx.x;
    if (idx < BATCH * HID) {
        g_hhi[idx] = __float2bfloat16(0.0f);
        g_hlo[idx] = __float2bfloat16(0.0f);
    }
    if (idx < BATCH * KHEADS * HID) g_c[idx] = 0.0f;
}

// ====================== recurrent gates GEMM (HMMA, split-bf16 fp32 emulation) ======================
// gates[b,g] = sum_k h[b,k]*Wh[k,g] + Wi[X[b,t],g] + bi[g] + bh[g]
// D = Ahi*Bhi + Ahi*Blo + Alo*Bhi (fp32 accum). BM=128, BN=128, KC=32, 256 thr, 2-stage cp.async.
#define KCC   32
#define KT    (HID / KCC)   // 32
#define ROWB  80            // padded smem row stride (64B data + 16B pad) — conflict-free ldmatrix
#define REG_A_HI 0
#define REG_A_LO 10240
#define REG_B_HI 20480
#define REG_B_LO 30720
#define STAGE    40960
#define SMEMSZ   (2 * STAGE)   // 81920

__global__ __launch_bounds__(256, 2)
void mma_gates_kernel(const int* __restrict__ X, const float* __restrict__ Wi, int t) {
    extern __shared__ char smem[];
    const uint32_t sb = smem_u32(smem);
    const int tid  = threadIdx.x;
    const int lane = tid & 31;
    const int wid  = tid >> 5;
    const int wm   = wid & 1;     // 2 warp rows  (64 M each)
    const int wn   = wid >> 1;    // 4 warp cols  (32 N each)
    const int m0 = blockIdx.y * 128;
    const int n0 = blockIdx.x * 128;

    // ---- cp.async source/dst mapping: thread -> (row, 2 of 4 16B chunks) in each region
    const int ldrow = tid >> 1;
    const int ldc   = (tid & 1) * 2;
    const __nv_bfloat16* aHiSrc = g_hhi    + (size_t)(m0 + ldrow) * HID + ldc * 8;
    const __nv_bfloat16* aLoSrc = g_hlo    + (size_t)(m0 + ldrow) * HID + ldc * 8;
    const __nv_bfloat16* bHiSrc = g_WhT_hi + (size_t)(n0 + ldrow) * HID + ldc * 8;
    const __nv_bfloat16* bLoSrc = g_WhT_lo + (size_t)(n0 + ldrow) * HID + ldc * 8;
    const uint32_t dRow = sb + (uint32_t)ldrow * ROWB + (uint32_t)ldc * 16;

    // ---- ldmatrix per-thread smem offsets
    const uint32_t aoff = (uint32_t)(wm * 64 + (lane & 15)) * ROWB + ((lane >> 4) & 1) * 16;
    const uint32_t boff = (uint32_t)(wn * 32 + ((lane >> 4) & 1) * 8 + (lane & 7)) * ROWB
                        + ((lane >> 3) & 1) * 16;

    float acc[4][4][4];
#pragma unroll
    for (int i = 0; i < 4; ++i)
#pragma unroll
        for (int j = 0; j < 4; ++j)
#pragma unroll
            for (int q = 0; q < 4; ++q) acc[i][j][q] = 0.0f;

    // ---- prologue: stage 0 <- k-chunk 0
    {
        const uint32_t d = dRow;
#pragma unroll
        for (int c = 0; c < 2; ++c) {
            cp_async16(d + REG_A_HI + c * 16, aHiSrc + c * 8);
            cp_async16(d + REG_A_LO + c * 16, aLoSrc + c * 8);
            cp_async16(d + REG_B_HI + c * 16, bHiSrc + c * 8);
            cp_async16(d + REG_B_LO + c * 16, bLoSrc + c * 8);
        }
        CP_COMMIT();
    }

#pragma unroll 1
    for (int kc = 0; kc < KT; ++kc) {
        const int s = kc & 1;
        if (kc + 1 < KT) {
            const uint32_t d = dRow + (uint32_t)(s ^ 1) * STAGE;
            const int ke = (kc + 1) * KCC;
#pragma unroll
            for (int c = 0; c < 2; ++c) {
                cp_async16(d + REG_A_HI + c * 16, aHiSrc + ke + c * 8);
                cp_async16(d + REG_A_LO + c * 16, aLoSrc + ke + c * 8);
                cp_async16(d + REG_B_HI + c * 16, bHiSrc + ke + c * 8);
                cp_async16(d + REG_B_LO + c * 16, bLoSrc + ke + c * 8);
            }
            CP_COMMIT();
            CP_WAIT(1);
        } else {
            CP_WAIT(0);
        }
        __syncthreads();

        const uint32_t sbase = sb + (uint32_t)s * STAGE;
#pragma unroll
        for (int ks = 0; ks < 2; ++ks) {
            const uint32_t kb = (uint32_t)ks * 32;
            uint32_t ahi[4][4], alo[4][4], bhi[2][4], blo[2][4];
#pragma unroll
            for (int mt = 0; mt < 4; ++mt)
                ldsm_x4(ahi[mt], sbase + REG_A_HI + aoff + (uint32_t)mt * (16 * ROWB) + kb);
#pragma unroll
            for (int p = 0; p < 2; ++p) {
                ldsm_x4(bhi[p], sbase + REG_B_HI + boff + (uint32_t)p * (16 * ROWB) + kb);
                ldsm_x4(blo[p], sbase + REG_B_LO + boff + (uint32_t)p * (16 * ROWB) + kb);
            }
#pragma unroll
            for (int mt = 0; mt < 4; ++mt)
                ldsm_x4(alo[mt], sbase + REG_A_LO + aoff + (uint32_t)mt * (16 * ROWB) + kb);

#pragma unroll
            for (int mt = 0; mt < 4; ++mt)
#pragma unroll
                for (int nt = 0; nt < 4; ++nt) {
                    const uint32_t* bh_ = &bhi[nt >> 1][(nt & 1) * 2];
                    const uint32_t* bl_ = &blo[nt >> 1][(nt & 1) * 2];
                    mma16816(acc[mt][nt], ahi[mt], bh_);
                    mma16816(acc[mt][nt], ahi[mt], bl_);
                    mma16816(acc[mt][nt], alo[mt], bh_);
                }
        }
        __syncthreads();
    }

    // ---- epilogue: + Wi[X[row,t]] + (bi+bh) -> g_gates, straight from C-fragments
    const int r_base = m0 + wm * 64 + (lane >> 2);
    const int c_base = n0 + wn * 32 + (lane & 3) * 2;
#pragma unroll
    for (int mt = 0; mt < 4; ++mt) {
        const int r0 = r_base + mt * 16;
        const int r1 = r0 + 8;
        const int xb0 = X[r0 * SEQ + t];
        const int xb1 = X[r1 * SEQ + t];
        const float* w0 = Wi + (size_t)xb0 * GDIM;
        const float* w1 = Wi + (size_t)xb1 * GDIM;
        float* o0 = g_gates + (size_t)r0 * GDIM;
        float* o1 = g_gates + (size_t)r1 * GDIM;
#pragma unroll
        for (int nt = 0; nt < 4; ++nt) {
            const int c = c_base + nt * 8;
            const float2 bs = *(const float2*)(g_bsum + c);
            const float2 wa = *(const float2*)(w0 + c);
            const float2 wb = *(const float2*)(w1 + c);
            float2 va, vb;
            va.x = acc[mt][nt][0] + wa.x + bs.x;
            va.y = acc[mt][nt][1] + wa.y + bs.y;
            vb.x = acc[mt][nt][2] + wb.x + bs.x;
            vb.y = acc[mt][nt][3] + wb.y + bs.y;
            *(float2*)(o0 + c) = va;
            *(float2*)(o1 + c) = vb;
        }
    }
}

// ---------------- pointwise LSTM update (activations + argmax head select) ----------------
__global__ void lstm_update_kernel() {
    const int idx = blockIdx.x * blockDim.x + threadIdx.x;  // 0 .. BATCH*HID-1
    const int b = idx >> 10;
    const int j = idx & (HID - 1);

    const float* gb = g_gates + (size_t)b * GDIM + j;
    float* cb = g_c + (size_t)(b * KHEADS) * HID + j;

    float omax = -3.402823466e38f;
    float csel = 0.0f;
#pragma unroll
    for (int k = 0; k < KHEADS; ++k) {
        const float gi = gb[k * 4096 + 0];
        const float gf = gb[k * 4096 + 1024];
        const float gg = gb[k * 4096 + 2048];
        const float go = gb[k * 4096 + 3072];
        const float iv = sigmoidf_(gi);
        const float fv = sigmoidf_(gf);
        const float gv = tanhf(gg);
        const float c  = fv * cb[k * HID] + iv * gv;
        cb[k * HID] = c;
        if (go > omax) { omax = go; csel = c; }  // strict > keeps first max (jnp.argmax)
    }
    const float h = sigmoidf_(omax) * tanhf(csel);
    g_h[idx] = h;
    const __nv_bfloat16 hi = __float2bfloat16(h);
    g_hhi[idx] = hi;
    g_hlo[idx] = __float2bfloat16(h - __bfloat162float(hi));
}

// ---------------- final logits GEMM: out = h @ Wl + bl (fp32 SIMT, runs once) ----------------
#define BM  128
#define BN  128
#define BKK 8
#define TM  8
#define TN  8

__global__ __launch_bounds__(256, 2)
void gemm_logits_kernel(const float* __restrict__ Wl,
                        const float* __restrict__ bl,
                        float* __restrict__ out)
{
    __shared__ float As[2][BKK][BM];
    __shared__ float Bs[2][BKK][BN];

    const float* __restrict__ A = g_h;
    const int m0  = blockIdx.y * BM;
    const int n0  = blockIdx.x * BN;
    const int tid = threadIdx.x;

    const int a_m = tid >> 1;
    const int a_k = (tid & 1) << 2;
    const int b_k = tid >> 5;
    const int b_n = (tid & 31) << 2;
    const int tx = tid & 15;
    const int ty = tid >> 4;

    float acc[TM][TN];
#pragma unroll
    for (int i = 0; i < TM; ++i)
#pragma unroll
        for (int j = 0; j < TN; ++j) acc[i][j] = 0.0f;

    {
        float4 av = *(const float4*)(A  + (m0 + a_m) * HID + a_k);
        float4 bv = *(const float4*)(Wl + b_k * HID + n0 + b_n);
        As[0][a_k + 0][a_m] = av.x; As[0][a_k + 1][a_m] = av.y;
        As[0][a_k + 2][a_m] = av.z; As[0][a_k + 3][a_m] = av.w;
        *(float4*)(&Bs[0][b_k][b_n]) = bv;
    }
    __syncthreads();

    const int KTl = HID / BKK;
#pragma unroll 1
    for (int kt = 0; kt < KTl; ++kt) {
        const int cur = kt & 1;
        float4 av, bv;
        if (kt + 1 < KTl) {
            const int kk = (kt + 1) * BKK;
            av = *(const float4*)(A  + (m0 + a_m) * HID + kk + a_k);
            bv = *(const float4*)(Wl + (kk + b_k) * HID + n0 + b_n);
        }
#pragma unroll
        for (int k = 0; k < BKK; ++k) {
            float ar[TM], br[TN];
#pragma unroll
            for (int i = 0; i < TM; ++i) ar[i] = As[cur][k][ty * TM + i];
#pragma unroll
            for (int j = 0; j < TN; ++j) br[j] = Bs[cur][k][tx * TN + j];
#pragma unroll
            for (int i = 0; i < TM; ++i)
#pragma unroll
                for (int j = 0; j < TN; ++j)
                    acc[i][j] = fmaf(ar[i], br[j], acc[i][j]);
        }
        if (kt + 1 < KTl) {
            const int nxt = cur ^ 1;
            As[nxt][a_k + 0][a_m] = av.x; As[nxt][a_k + 1][a_m] = av.y;
            As[nxt][a_k + 2][a_m] = av.z; As[nxt][a_k + 3][a_m] = av.w;
            *(float4*)(&Bs[nxt][b_k][b_n]) = bv;
            __syncthreads();
        }
    }

#pragma unroll
    for (int i = 0; i < TM; ++i) {
        const int gm = m0 + ty * TM + i;
        const int gn = n0 + tx * TN;
        float* orow = out + gm * HID + gn;
#pragma unroll
        for (int j = 0; j < TN; j += 4) {
            float4 b1 = *(const float4*)(bl + gn + j);
            float4 o;
            o.x = acc[i][j + 0] + b1.x;
            o.y = acc[i][j + 1] + b1.y;
            o.z = acc[i][j + 2] + b1.z;
            o.w = acc[i][j + 3] + b1.w;
            *(float4*)(orow + j) = o;
        }
    }
}

// ---------------- in-place log_softmax over rows of [BATCH, 1024] ----------------
__global__ void logsoftmax_kernel(float* __restrict__ out) {
    __shared__ float red[256];
    const int b = blockIdx.x;
    const int tid = threadIdx.x;
    float* row = out + b * HID;

    const float v0 = row[tid];
    const float v1 = row[tid + 256];
    const float v2 = row[tid + 512];
    const float v3 = row[tid + 768];

    float m = fmaxf(fmaxf(v0, v1), fmaxf(v2, v3));
    red[tid] = m;
    __syncthreads();
    for (int s = 128; s > 0; s >>= 1) {
        if (tid < s) red[tid] = fmaxf(red[tid], red[tid + s]);
        __syncthreads();
    }
    m = red[0];
    __syncthreads();

    float e = expf(v0 - m) + expf(v1 - m) + expf(v2 - m) + expf(v3 - m);
    red[tid] = e;
    __syncthreads();
    for (int s = 128; s > 0; s >>= 1) {
        if (tid < s) red[tid] += red[tid + s];
        __syncthreads();
    }
    const float lse = m + logf(red[0]);

    row[tid]       = v0 - lse;
    row[tid + 256] = v1 - lse;
    row[tid + 512] = v2 - lse;
    row[tid + 768] = v3 - lse;
}

// ---------------- launcher (graph-capturable: kernel launches only) ----------------
extern "C" void kernel_launch(void* const* d_in, const int* in_sizes, int n_in,
                              void* d_out, int out_size) {
    const int*   X  = (const int*)  d_in[0];
    const float* Wi = (const float*)d_in[1];
    const float* bi = (const float*)d_in[2];
    const float* Wh = (const float*)d_in[3];
    const float* bh = (const float*)d_in[4];
    const float* Wl = (const float*)d_in[5];
    const float* bl = (const float*)d_in[6];
    float* out = (float*)d_out;

    (void)in_sizes; (void)n_in; (void)out_size;

    cudaFuncSetAttribute(mma_gates_kernel,
                         cudaFuncAttributeMaxDynamicSharedMemorySize, SMEMSZ);

    // prepass: Wh^T hi/lo bf16, bias fold, state init
    prep_wht_kernel<<<dim3(GDIM / 32, HID / 32), dim3(32, 8)>>>(Wh);
    prep_bsum_kernel<<<GDIM / 256, 256>>>(bi, bh);
    zero_kernel<<<(BATCH * KHEADS * HID + 255) / 256, 256>>>();

    const dim3 gg(GDIM / 128, BATCH / 128);   // (128, 2) = 256 CTAs, one wave @ occ 2
    for (int t = 0; t < SEQ; ++t) {
        mma_gates_kernel<<<gg, 256, SMEMSZ>>>(X, Wi, t);
        lstm_update_kernel<<<(BATCH * HID) / 256, 256>>>();
    }

    gemm_logits_kernel<<<dim3(HID / BN, BATCH / BM), 256>>>(Wl, bl, out);
    logsoftmax_kernel<<<BATCH, 256>>>(out);
}